// round 7
// baseline (speedup 1.0000x reference)
#include <cuda_runtime.h>
#include <cuda_bf16.h>
#include <cstdint>

#define B_DIM 4
#define S_DIM 4096
#define E_DIM 256
#define BS_DIM (B_DIM * S_DIM)

// ---------------- scratch (static __device__, no allocations) ----------------
__device__ __nv_bfloat16 g_x_bf[BS_DIM * E_DIM];                  // 8 MB
__device__ __nv_bfloat16 g_WqT[E_DIM * E_DIM];                    // W^T bf16
__device__ __nv_bfloat16 g_WkT[E_DIM * E_DIM];
__device__ __nv_bfloat16 g_q[BS_DIM * E_DIM];                     // 8 MB
__device__ __nv_bfloat16 g_k[BS_DIM * E_DIM];                     // 8 MB
__device__ __nv_bfloat16 g_E[(size_t)B_DIM * S_DIM * S_DIM];      // 134 MB exp-scores
__device__ float g_Z[B_DIM * S_DIM];                              // softmax row sums
__device__ float g_u[B_DIM * S_DIM];                              // column means of attn
__device__ float g_y[B_DIM * E_DIM];                              // u^T x

// ================= low-level helpers =================
__device__ __forceinline__ uint32_t smem_u32(const void* p) {
    uint32_t a;
    asm("{ .reg .u64 t; cvta.to.shared.u64 t, %1; cvt.u32.u64 %0, t; }" : "=r"(a) : "l"(p));
    return a;
}

__device__ __forceinline__ void ldsm4(uint32_t (&r)[4], uint32_t addr) {
    asm volatile("ldmatrix.sync.aligned.m8n8.x4.shared.b16 {%0,%1,%2,%3}, [%4];"
                 : "=r"(r[0]), "=r"(r[1]), "=r"(r[2]), "=r"(r[3]) : "r"(addr));
}

__device__ __forceinline__ void mma16816(float (&d)[4], const uint32_t (&a)[4],
                                         uint32_t b0, uint32_t b1) {
    asm volatile("mma.sync.aligned.m16n8k16.row.col.f32.bf16.bf16.f32 "
                 "{%0,%1,%2,%3}, {%4,%5,%6,%7}, {%8,%9}, {%0,%1,%2,%3};"
                 : "+f"(d[0]), "+f"(d[1]), "+f"(d[2]), "+f"(d[3])
                 : "r"(a[0]), "r"(a[1]), "r"(a[2]), "r"(a[3]), "r"(b0), "r"(b1));
}

// swizzled address inside a 128-row x 256-col bf16 tile (blocked SW128 atoms)
__device__ __forceinline__ uint32_t swz128(uint32_t base, int r, int c16) {
    return base + (((uint32_t)(c16 >> 3)) << 14) + (((uint32_t)(r >> 3)) << 10)
                + (((uint32_t)(r & 7)) << 7) + (((uint32_t)((c16 ^ r) & 7)) << 4);
}

// Load a 128x256-bf16 tile (64KB) into the swizzled layout via cp.async (16B chunks).
template <int NT>
__device__ __forceinline__ void load_tile_async(uint32_t sm_base,
                                                const __nv_bfloat16* __restrict__ src,
                                                int tid) {
    #pragma unroll
    for (int it = 0; it < 4096 / NT; ++it) {
        int idx = it * NT + tid;           // 0..4095 16B chunks
        int r = idx >> 5;                  // row 0..127
        int g = idx & 31;                  // chunk 0..31
        uint32_t dst = swz128(sm_base, r, g);
        const void* gp = (const void*)(src + (size_t)r * E_DIM + g * 8);
        asm volatile("cp.async.cg.shared.global [%0], [%1], 16;" :: "r"(dst), "l"(gp));
    }
}
#define CPASYNC_COMMIT() asm volatile("cp.async.commit_group;" ::: "memory")
#define CPASYNC_WAIT0() asm volatile("cp.async.wait_group 0;" ::: "memory")

// warp-tile 32x32 MMA over K=256: acc[2][4][4] += A(rows mw..) * B(cols nw..)^T
__device__ __forceinline__ void mma_tile32(uint32_t Ab, uint32_t Bb, float (&acc)[2][4][4],
                                           int mw, int nw, int lane) {
    const int lane15 = lane & 15, laneh = lane >> 4;
    #pragma unroll
    for (int ks = 0; ks < 16; ++ks) {
        const int c16 = ks * 2 + laneh;
        uint32_t a[2][4], bf[2][4];
        #pragma unroll
        for (int i = 0; i < 2; ++i)
            ldsm4(a[i], swz128(Ab, mw + i * 16 + lane15, c16));
        #pragma unroll
        for (int j2 = 0; j2 < 2; ++j2)
            ldsm4(bf[j2], swz128(Bb, nw + j2 * 16 + lane15, c16));
        #pragma unroll
        for (int i = 0; i < 2; ++i)
            #pragma unroll
            for (int j = 0; j < 4; ++j)
                mma16816(acc[i][j], a[i], bf[j >> 1][j & 1], bf[j >> 1][(j & 1) + 2]);
    }
}

// ---------------- fp32 -> bf16 conversion (+ W transposes) + zero-init ----------------
__global__ void convert_kernel(const float* __restrict__ x,
                               const float* __restrict__ Wq,
                               const float* __restrict__ Wk) {
    const int tid = blockIdx.x * blockDim.x + threadIdx.x;
    const int nthr = gridDim.x * blockDim.x;
    for (int i = tid; i < (BS_DIM * E_DIM) / 4; i += nthr) {
        float4 f = reinterpret_cast<const float4*>(x)[i];
        __nv_bfloat162 lo = __floats2bfloat162_rn(f.x, f.y);
        __nv_bfloat162 hi = __floats2bfloat162_rn(f.z, f.w);
        uint2 pkt;
        pkt.x = *reinterpret_cast<uint32_t*>(&lo);
        pkt.y = *reinterpret_cast<uint32_t*>(&hi);
        reinterpret_cast<uint2*>(g_x_bf)[i] = pkt;
    }
    if (tid < E_DIM * E_DIM) {
        int k = tid >> 8, n = tid & 255;
        g_WqT[n * E_DIM + k] = __float2bfloat16(Wq[tid]);
        g_WkT[n * E_DIM + k] = __float2bfloat16(Wk[tid]);
    }
    if (tid < B_DIM * S_DIM) { g_Z[tid] = 0.f; g_u[tid] = 0.f; }
    if (tid < B_DIM * E_DIM) g_y[tid] = 0.f;
}

// ---------------- Q/K projections (fused): per m-block, compute q & k, both n-halves ----
#define PROJ_SMEM (196608 + 1024)
__global__ void __launch_bounds__(256) proj_tc_kernel(const float* __restrict__ bq,
                                                      const float* __restrict__ bk) {
    extern __shared__ char dynsm[];
    __shared__ float sb[4][128];
    const uint32_t base = (smem_u32(dynsm) + 1023u) & ~1023u;
    const uint32_t Ab = base;
    const uint32_t Bbuf[2] = { base + 65536u, base + 131072u };

    const int tid = threadIdx.x;
    const int lane = tid & 31, wid = tid >> 5;
    const int mw = (wid & 1) * 64, nw = (wid >> 1) * 32;
    const int m0 = blockIdx.x * 128;

    for (int i = tid; i < 512; i += 256)
        sb[i >> 7][i & 127] = (i >= 256 ? bk : bq)[((i >> 7) & 1) * 128 + (i & 127)];

    load_tile_async<256>(Ab, g_x_bf + (size_t)m0 * E_DIM, tid);
    load_tile_async<256>(Bbuf[0], g_WqT, tid);
    CPASYNC_COMMIT();

    #pragma unroll 1
    for (int it = 0; it < 4; ++it) {          // it: (which<<1)|nblk
        const int which = it >> 1, nblk = it & 1;
        const int n0 = nblk * 128;
        CPASYNC_WAIT0();
        __syncthreads();
        if (it + 1 < 4) {
            const int wn = (it + 1) >> 1, nb = (it + 1) & 1;
            load_tile_async<256>(Bbuf[(it + 1) & 1],
                                 (wn ? g_WkT : g_WqT) + (size_t)(nb * 128) * E_DIM, tid);
            CPASYNC_COMMIT();
        }

        float acc[2][2][4][4] = {};
        #pragma unroll
        for (int mh = 0; mh < 2; ++mh)
            mma_tile32(Ab, Bbuf[it & 1], acc[mh], mw + mh * 32, nw, lane);

        __nv_bfloat16* outp = which ? g_k : g_q;
        #pragma unroll
        for (int mh = 0; mh < 2; ++mh) {
            #pragma unroll
            for (int i = 0; i < 2; ++i) {
                #pragma unroll
                for (int h = 0; h < 2; ++h) {
                    const int r = m0 + mw + mh * 32 + i * 16 + (lane >> 2) + h * 8;
                    #pragma unroll
                    for (int j = 0; j < 4; ++j) {
                        const int cl = nw + j * 8 + (lane & 3) * 2;
                        float v0 = acc[mh][i][j][2 * h]     + sb[it][cl];
                        float v1 = acc[mh][i][j][2 * h + 1] + sb[it][cl + 1];
                        *reinterpret_cast<__nv_bfloat162*>(&outp[(size_t)r * E_DIM + n0 + cl]) =
                            __floats2bfloat162_rn(v0, v1);
                    }
                }
            }
        }
    }
}

// ---------------- scores: E = exp(q k^T / 16), fused row sums -> g_Z ----------------
// grid (32, 4). 512 threads, 16 warps 4x4, warp tile 32x32 on EACH tile of a pair.
// Pair scheme: A-fragments shared across two n-tiles (LDSM -25%); loads for the next
// pair are issued right after the mma phase and overlap the register-only epilogue.
#define SCORES_SMEM (196608 + 1024)
__global__ void __launch_bounds__(512, 1) scores_mma_kernel() {
    extern __shared__ char dynsm[];
    const uint32_t base = (smem_u32(dynsm) + 1023u) & ~1023u;
    const uint32_t Ab = base;
    const uint32_t B0 = base + 65536u, B1 = base + 131072u;

    const int tid = threadIdx.x;
    const int lane = tid & 31, wid = tid >> 5;
    const int mw = (wid & 3) * 32, nw = (wid >> 2) * 32;
    const int m0 = blockIdx.x * 128;
    const int b = blockIdx.y;

    const __nv_bfloat16* Aq = g_q + (size_t)b * S_DIM * E_DIM;
    const __nv_bfloat16* Bk = g_k + (size_t)b * S_DIM * E_DIM;

    load_tile_async<512>(Ab, Aq + (size_t)m0 * E_DIM, tid);
    load_tile_async<512>(B0, Bk, tid);
    load_tile_async<512>(B1, Bk + (size_t)128 * E_DIM, tid);
    CPASYNC_COMMIT();

    float rs[4] = {0.f, 0.f, 0.f, 0.f};
    const float SCALE = 0.09016844f;  // log2(e) / 16
    const int lane15 = lane & 15, laneh = lane >> 4;

    #pragma unroll 1
    for (int p = 0; p < 16; ++p) {
        CPASYNC_WAIT0();
        __syncthreads();

        float acc[2][2][4][4] = {};   // [tile][i][j][v]

        #pragma unroll
        for (int ks = 0; ks < 16; ++ks) {
            const int c16 = ks * 2 + laneh;
            uint32_t a[2][4], f0[2][4], f1[2][4];
            ldsm4(a[0], swz128(Ab, mw + lane15, c16));
            ldsm4(a[1], swz128(Ab, mw + 16 + lane15, c16));
            ldsm4(f0[0], swz128(B0, nw + lane15, c16));
            ldsm4(f0[1], swz128(B0, nw + 16 + lane15, c16));
            ldsm4(f1[0], swz128(B1, nw + lane15, c16));
            ldsm4(f1[1], swz128(B1, nw + 16 + lane15, c16));
            #pragma unroll
            for (int i = 0; i < 2; ++i) {
                #pragma unroll
                for (int j = 0; j < 4; ++j) {
                    mma16816(acc[0][i][j], a[i], f0[j >> 1][j & 1], f0[j >> 1][(j & 1) + 2]);
                    mma16816(acc[1][i][j], a[i], f1[j >> 1][j & 1], f1[j >> 1][(j & 1) + 2]);
                }
            }
        }
        __syncthreads();   // all warps done reading B0/B1

        if (p + 1 < 16) {  // issue next pair ASAP; epilogue below overlaps the flight
            load_tile_async<512>(B0, Bk + (size_t)(2 * p + 2) * 128 * E_DIM, tid);
            load_tile_async<512>(B1, Bk + (size_t)(2 * p + 3) * 128 * E_DIM, tid);
            CPASYNC_COMMIT();
        }

        // epilogue (registers + global only): exp, bf16 store, row sums
        #pragma unroll
        for (int t = 0; t < 2; ++t) {
            const int n = 2 * p + t;
            #pragma unroll
            for (int i = 0; i < 2; ++i) {
                #pragma unroll
                for (int h = 0; h < 2; ++h) {
                    const int r = m0 + mw + i * 16 + (lane >> 2) + h * 8;
                    const size_t rowb = ((size_t)b * S_DIM + r) * S_DIM
                                      + (size_t)n * 128 + nw + (lane & 3) * 2;
                    float partial = 0.f;
                    #pragma unroll
                    for (int j = 0; j < 4; ++j) {
                        float v0, v1;
                        asm("ex2.approx.ftz.f32 %0, %1;" : "=f"(v0) : "f"(acc[t][i][j][2 * h] * SCALE));
                        asm("ex2.approx.ftz.f32 %0, %1;" : "=f"(v1) : "f"(acc[t][i][j][2 * h + 1] * SCALE));
                        partial += v0 + v1;
                        *reinterpret_cast<__nv_bfloat162*>(&g_E[rowb + j * 8]) =
                            __floats2bfloat162_rn(v0, v1);
                    }
                    rs[i * 2 + h] += partial;
                }
            }
        }
    }

    // reduce row sums over the 4 lanes sharing a row, then atomically publish
    #pragma unroll
    for (int i = 0; i < 4; ++i) {
        rs[i] += __shfl_xor_sync(0xffffffffu, rs[i], 1);
        rs[i] += __shfl_xor_sync(0xffffffffu, rs[i], 2);
    }
    if ((lane & 3) == 0) {
        #pragma unroll
        for (int i = 0; i < 4; ++i) {
            const int r = m0 + mw + (i >> 1) * 16 + (i & 1) * 8 + (lane >> 2);
            atomicAdd(&g_Z[b * S_DIM + r], rs[i]);
        }
    }
}

// ---------------- u[b,t] = (1/S) * sum_s E[b,s,t] / Z[b,s] ----------------
// grid (2, 64, 4) = 512 CTAs; s-chunk 64 rows (round-5 optimum).
__global__ void __launch_bounds__(256) colreduce_kernel() {
    const int b  = blockIdx.z;
    const int s0 = blockIdx.y * 64;
    const int t0 = blockIdx.x * 2048 + threadIdx.x * 8;
    __shared__ float invZ[64];
    if (threadIdx.x < 64)
        invZ[threadIdx.x] = 1.f / g_Z[b * S_DIM + s0 + threadIdx.x];
    __syncthreads();
    float a[8] = {0.f, 0.f, 0.f, 0.f, 0.f, 0.f, 0.f, 0.f};
    const __nv_bfloat16* Ep = g_E + ((size_t)b * S_DIM + s0) * S_DIM + t0;
    #pragma unroll 8
    for (int s = 0; s < 64; ++s) {
        uint4 pkt = *reinterpret_cast<const uint4*>(&Ep[(size_t)s * S_DIM]);
        const __nv_bfloat162* p2 = reinterpret_cast<const __nv_bfloat162*>(&pkt);
        float w = invZ[s];
        #pragma unroll
        for (int j = 0; j < 4; ++j) {
            float2 f = __bfloat1622float2(p2[j]);
            a[2 * j]     += f.x * w;
            a[2 * j + 1] += f.y * w;
        }
    }
    const float sc = 1.f / S_DIM;
    #pragma unroll
    for (int j = 0; j < 8; ++j)
        atomicAdd(&g_u[b * S_DIM + t0 + j], a[j] * sc);
}

// ---------------- y[b,:] = sum_t u[b,t] * x[b,t,:]  (fp32-exact V path) ----------------
__global__ void __launch_bounds__(256) pool_kernel(const float* __restrict__ x) {
    const int b = blockIdx.y, seg = blockIdx.x;
    const int e = threadIdx.x;
    __shared__ float us[128];
    if (e < 128) us[e] = g_u[b * S_DIM + seg * 128 + e];
    __syncthreads();
    float acc = 0.f;
    const float* xp = x + ((size_t)b * S_DIM + seg * 128) * E_DIM + e;
    #pragma unroll 8
    for (int tt = 0; tt < 128; ++tt) acc += us[tt] * xp[(size_t)tt * E_DIM];
    atomicAdd(&g_y[b * E_DIM + e], acc);
}

// ---------------- out[b,:] = y[b,:] @ Wv + bv ----------------
__global__ void __launch_bounds__(256) out_kernel(const float* __restrict__ Wv,
                                                  const float* __restrict__ bv,
                                                  float* __restrict__ out) {
    const int b = blockIdx.x, e = threadIdx.x;
    __shared__ float ys[256];
    ys[e] = g_y[b * E_DIM + e];
    __syncthreads();
    float acc = 0.f;
    #pragma unroll 8
    for (int j = 0; j < 256; ++j) acc += ys[j] * Wv[j * E_DIM + e];
    out[b * E_DIM + e] = acc + bv[e];
}

// ---------------- launch ----------------
extern "C" void kernel_launch(void* const* d_in, const int* in_sizes, int n_in,
                              void* d_out, int out_size) {
    (void)in_sizes; (void)n_in; (void)out_size;
    const float* x  = (const float*)d_in[0];
    const float* Wq = (const float*)d_in[1];
    const float* bq = (const float*)d_in[2];
    const float* Wk = (const float*)d_in[3];
    const float* bk = (const float*)d_in[4];
    const float* Wv = (const float*)d_in[5];
    const float* bv = (const float*)d_in[6];
    float* out = (float*)d_out;

    cudaFuncSetAttribute(scores_mma_kernel,
                         cudaFuncAttributeMaxDynamicSharedMemorySize, SCORES_SMEM);
    cudaFuncSetAttribute(proj_tc_kernel,
                         cudaFuncAttributeMaxDynamicSharedMemorySize, PROJ_SMEM);

    convert_kernel<<<2048, 256>>>(x, Wq, Wk);
    proj_tc_kernel<<<BS_DIM / 128, 256, PROJ_SMEM>>>(bq, bk);
    scores_mma_kernel<<<dim3(S_DIM / 128, B_DIM), 512, SCORES_SMEM>>>();
    colreduce_kernel<<<dim3(2, 64, B_DIM), 256>>>();
    pool_kernel<<<dim3(S_DIM / 128, B_DIM), 256>>>(x);
    out_kernel<<<B_DIM, 256>>>(Wv, bv, out);
}

// round 8
// speedup vs baseline: 1.1118x; 1.1118x over previous
#include <cuda_runtime.h>
#include <cuda_bf16.h>
#include <cstdint>

#define B_DIM 4
#define S_DIM 4096
#define E_DIM 256
#define BS_DIM (B_DIM * S_DIM)

// ---------------- scratch (static __device__, no allocations) ----------------
__device__ __nv_bfloat16 g_WqT[E_DIM * E_DIM];                    // W^T bf16
__device__ __nv_bfloat16 g_WkT[E_DIM * E_DIM];
__device__ __nv_bfloat16 g_q[BS_DIM * E_DIM];                     // 8 MB
__device__ __nv_bfloat16 g_k[BS_DIM * E_DIM];                     // 8 MB
__device__ __nv_bfloat16 g_E[(size_t)B_DIM * S_DIM * S_DIM];      // 134 MB exp-scores
__device__ float g_Z[B_DIM * S_DIM];                              // softmax row sums
__device__ float g_u[B_DIM * S_DIM];                              // column means of attn
__device__ float g_y[B_DIM * E_DIM];                              // u^T x

// ================= low-level helpers =================
__device__ __forceinline__ uint32_t smem_u32(const void* p) {
    uint32_t a;
    asm("{ .reg .u64 t; cvta.to.shared.u64 t, %1; cvt.u32.u64 %0, t; }" : "=r"(a) : "l"(p));
    return a;
}

__device__ __forceinline__ void ldsm4(uint32_t (&r)[4], uint32_t addr) {
    asm volatile("ldmatrix.sync.aligned.m8n8.x4.shared.b16 {%0,%1,%2,%3}, [%4];"
                 : "=r"(r[0]), "=r"(r[1]), "=r"(r[2]), "=r"(r[3]) : "r"(addr));
}

__device__ __forceinline__ void mma16816(float (&d)[4], const uint32_t (&a)[4],
                                         uint32_t b0, uint32_t b1) {
    asm volatile("mma.sync.aligned.m16n8k16.row.col.f32.bf16.bf16.f32 "
                 "{%0,%1,%2,%3}, {%4,%5,%6,%7}, {%8,%9}, {%0,%1,%2,%3};"
                 : "+f"(d[0]), "+f"(d[1]), "+f"(d[2]), "+f"(d[3])
                 : "r"(a[0]), "r"(a[1]), "r"(a[2]), "r"(a[3]), "r"(b0), "r"(b1));
}

// swizzled address inside a 128-row x 256-col bf16 tile (blocked SW128 atoms)
__device__ __forceinline__ uint32_t swz128(uint32_t base, int r, int c16) {
    return base + (((uint32_t)(c16 >> 3)) << 14) + (((uint32_t)(r >> 3)) << 10)
                + (((uint32_t)(r & 7)) << 7) + (((uint32_t)((c16 ^ r) & 7)) << 4);
}

// Load a 128x256-bf16 tile (64KB) into the swizzled layout via cp.async (16B chunks).
template <int NT>
__device__ __forceinline__ void load_tile_async(uint32_t sm_base,
                                                const __nv_bfloat16* __restrict__ src,
                                                int tid) {
    #pragma unroll
    for (int it = 0; it < 4096 / NT; ++it) {
        int idx = it * NT + tid;           // 0..4095 16B chunks
        int r = idx >> 5;                  // row 0..127
        int g = idx & 31;                  // chunk 0..31
        uint32_t dst = swz128(sm_base, r, g);
        const void* gp = (const void*)(src + (size_t)r * E_DIM + g * 8);
        asm volatile("cp.async.cg.shared.global [%0], [%1], 16;" :: "r"(dst), "l"(gp));
    }
}
#define CPASYNC_COMMIT() asm volatile("cp.async.commit_group;" ::: "memory")
#define CPASYNC_WAIT0() asm volatile("cp.async.wait_group 0;" ::: "memory")

// warp-tile 32x32 MMA over K=256: acc[2][4][4] += A(rows mw..) * B(cols nw..)^T
__device__ __forceinline__ void mma_tile32(uint32_t Ab, uint32_t Bb, float (&acc)[2][4][4],
                                           int mw, int nw, int lane) {
    const int lane15 = lane & 15, laneh = lane >> 4;
    #pragma unroll
    for (int ks = 0; ks < 16; ++ks) {
        const int c16 = ks * 2 + laneh;
        uint32_t a[2][4], bf[2][4];
        #pragma unroll
        for (int i = 0; i < 2; ++i)
            ldsm4(a[i], swz128(Ab, mw + i * 16 + lane15, c16));
        #pragma unroll
        for (int j2 = 0; j2 < 2; ++j2)
            ldsm4(bf[j2], swz128(Bb, nw + j2 * 16 + lane15, c16));
        #pragma unroll
        for (int i = 0; i < 2; ++i)
            #pragma unroll
            for (int j = 0; j < 4; ++j)
                mma16816(acc[i][j], a[i], bf[j >> 1][j & 1], bf[j >> 1][(j & 1) + 2]);
    }
}

// ---------------- W transposes (fp32 -> bf16) + zero-init ----------------
__global__ void convert_kernel(const float* __restrict__ Wq,
                               const float* __restrict__ Wk) {
    const int tid = blockIdx.x * blockDim.x + threadIdx.x;
    if (tid < E_DIM * E_DIM) {
        int k = tid >> 8, n = tid & 255;
        g_WqT[n * E_DIM + k] = __float2bfloat16(Wq[tid]);
        g_WkT[n * E_DIM + k] = __float2bfloat16(Wk[tid]);
    }
    if (tid < B_DIM * S_DIM) { g_Z[tid] = 0.f; g_u[tid] = 0.f; }
    if (tid < B_DIM * E_DIM) g_y[tid] = 0.f;
}

// ---------------- Q/K projections (fused + inline x conversion) ----------------
// grid (BS/128) = 128 CTAs; per m-block: convert x tile fp32->bf16 into swizzled A,
// then compute q & k for both n-halves with W^T slices double-buffered.
#define PROJ_SMEM (196608 + 1024)
__global__ void __launch_bounds__(256) proj_tc_kernel(const float* __restrict__ x,
                                                      const float* __restrict__ bq,
                                                      const float* __restrict__ bk) {
    extern __shared__ char dynsm[];
    __shared__ float sb[4][128];
    const uint32_t base = (smem_u32(dynsm) + 1023u) & ~1023u;
    const uint32_t Ab = base;
    const uint32_t Bbuf[2] = { base + 65536u, base + 131072u };
    char* Achar = dynsm + (int)(base - smem_u32(dynsm));

    const int tid = threadIdx.x;
    const int lane = tid & 31, wid = tid >> 5;
    const int mw = (wid & 1) * 64, nw = (wid >> 1) * 32;
    const int m0 = blockIdx.x * 128;

    for (int i = tid; i < 512; i += 256)
        sb[i >> 7][i & 127] = (i >= 256 ? bk : bq)[((i >> 7) & 1) * 128 + (i & 127)];

    // start W prefetch first so its latency overlaps the x conversion
    load_tile_async<256>(Bbuf[0], g_WqT, tid);
    CPASYNC_COMMIT();

    // inline conversion: x fp32 tile -> bf16 swizzled A (registers, plain LDG/STS)
    const float* xp = x + (size_t)m0 * E_DIM;
    #pragma unroll
    for (int it = 0; it < 16; ++it) {
        int idx = it * 256 + tid;          // 16B bf16 chunk index
        int r = idx >> 5, g = idx & 31;
        const float4* s = reinterpret_cast<const float4*>(xp + (size_t)r * E_DIM + g * 8);
        float4 f0 = s[0], f1 = s[1];
        __nv_bfloat162 h0 = __floats2bfloat162_rn(f0.x, f0.y);
        __nv_bfloat162 h1 = __floats2bfloat162_rn(f0.z, f0.w);
        __nv_bfloat162 h2 = __floats2bfloat162_rn(f1.x, f1.y);
        __nv_bfloat162 h3 = __floats2bfloat162_rn(f1.z, f1.w);
        uint4 pkt;
        pkt.x = *reinterpret_cast<uint32_t*>(&h0);
        pkt.y = *reinterpret_cast<uint32_t*>(&h1);
        pkt.z = *reinterpret_cast<uint32_t*>(&h2);
        pkt.w = *reinterpret_cast<uint32_t*>(&h3);
        *reinterpret_cast<uint4*>(Achar + (swz128(0, r, g))) = pkt;
    }

    #pragma unroll 1
    for (int it = 0; it < 4; ++it) {          // it: (which<<1)|nblk
        const int which = it >> 1, nblk = it & 1;
        const int n0 = nblk * 128;
        CPASYNC_WAIT0();
        __syncthreads();
        if (it + 1 < 4) {
            const int wn = (it + 1) >> 1, nb = (it + 1) & 1;
            load_tile_async<256>(Bbuf[(it + 1) & 1],
                                 (wn ? g_WkT : g_WqT) + (size_t)(nb * 128) * E_DIM, tid);
            CPASYNC_COMMIT();
        }

        float acc[2][2][4][4] = {};
        #pragma unroll
        for (int mh = 0; mh < 2; ++mh)
            mma_tile32(Ab, Bbuf[it & 1], acc[mh], mw + mh * 32, nw, lane);

        __nv_bfloat16* outp = which ? g_k : g_q;
        #pragma unroll
        for (int mh = 0; mh < 2; ++mh) {
            #pragma unroll
            for (int i = 0; i < 2; ++i) {
                #pragma unroll
                for (int h = 0; h < 2; ++h) {
                    const int r = m0 + mw + mh * 32 + i * 16 + (lane >> 2) + h * 8;
                    #pragma unroll
                    for (int j = 0; j < 4; ++j) {
                        const int cl = nw + j * 8 + (lane & 3) * 2;
                        float v0 = acc[mh][i][j][2 * h]     + sb[it][cl];
                        float v1 = acc[mh][i][j][2 * h + 1] + sb[it][cl + 1];
                        *reinterpret_cast<__nv_bfloat162*>(&outp[(size_t)r * E_DIM + n0 + cl]) =
                            __floats2bfloat162_rn(v0, v1);
                    }
                }
            }
        }
    }
}

// ---------------- scores: E = exp(q k^T / 16), fused row sums -> g_Z ----------------
// grid (32, 4). 512 threads, 16 warps 4x4, warp tile 32x32. Single barrier per tile.
// (round-5 configuration — measured local optimum)
#define SCORES_SMEM (196608 + 1024)
__global__ void __launch_bounds__(512, 1) scores_mma_kernel() {
    extern __shared__ char dynsm[];
    const uint32_t base = (smem_u32(dynsm) + 1023u) & ~1023u;
    const uint32_t Ab = base;
    const uint32_t Bbuf[2] = { base + 65536u, base + 131072u };

    const int tid = threadIdx.x;
    const int lane = tid & 31, wid = tid >> 5;
    const int mw = (wid & 3) * 32, nw = (wid >> 2) * 32;
    const int m0 = blockIdx.x * 128;
    const int b = blockIdx.y;

    const __nv_bfloat16* Aq = g_q + (size_t)b * S_DIM * E_DIM;
    const __nv_bfloat16* Bk = g_k + (size_t)b * S_DIM * E_DIM;

    load_tile_async<512>(Ab, Aq + (size_t)m0 * E_DIM, tid);
    load_tile_async<512>(Bbuf[0], Bk, tid);
    CPASYNC_COMMIT();

    float rs[4] = {0.f, 0.f, 0.f, 0.f};
    const float SCALE = 0.09016844f;  // log2(e) / 16

    #pragma unroll 1
    for (int n = 0; n < 32; ++n) {
        CPASYNC_WAIT0();
        __syncthreads();
        if (n + 1 < 32) {
            load_tile_async<512>(Bbuf[(n + 1) & 1], Bk + (size_t)(n + 1) * 128 * E_DIM, tid);
            CPASYNC_COMMIT();
        }

        float acc[2][4][4] = {};
        mma_tile32(Ab, Bbuf[n & 1], acc, mw, nw, lane);

        // epilogue: exp(score/16) -> bf16 store + row-sum accumulation
        #pragma unroll
        for (int i = 0; i < 2; ++i) {
            #pragma unroll
            for (int h = 0; h < 2; ++h) {
                const int r = m0 + mw + i * 16 + (lane >> 2) + h * 8;
                const size_t rowb = ((size_t)b * S_DIM + r) * S_DIM
                                  + (size_t)n * 128 + nw + (lane & 3) * 2;
                float partial = 0.f;
                #pragma unroll
                for (int j = 0; j < 4; ++j) {
                    float v0, v1;
                    asm("ex2.approx.ftz.f32 %0, %1;" : "=f"(v0) : "f"(acc[i][j][2 * h] * SCALE));
                    asm("ex2.approx.ftz.f32 %0, %1;" : "=f"(v1) : "f"(acc[i][j][2 * h + 1] * SCALE));
                    partial += v0 + v1;
                    *reinterpret_cast<__nv_bfloat162*>(&g_E[rowb + j * 8]) =
                        __floats2bfloat162_rn(v0, v1);
                }
                rs[i * 2 + h] += partial;
            }
        }
    }

    // reduce row sums over the 4 lanes sharing a row, then atomically publish
    #pragma unroll
    for (int i = 0; i < 4; ++i) {
        rs[i] += __shfl_xor_sync(0xffffffffu, rs[i], 1);
        rs[i] += __shfl_xor_sync(0xffffffffu, rs[i], 2);
    }
    if ((lane & 3) == 0) {
        #pragma unroll
        for (int i = 0; i < 4; ++i) {
            const int r = m0 + mw + (i >> 1) * 16 + (i & 1) * 8 + (lane >> 2);
            atomicAdd(&g_Z[b * S_DIM + r], rs[i]);
        }
    }
}

// ---------------- u[b,t] = (1/S) * sum_s E[b,s,t] / Z[b,s] ----------------
// grid (2, 64, 4) = 512 CTAs; s-chunk 64 rows (measured optimum).
__global__ void __launch_bounds__(256) colreduce_kernel() {
    const int b  = blockIdx.z;
    const int s0 = blockIdx.y * 64;
    const int t0 = blockIdx.x * 2048 + threadIdx.x * 8;
    __shared__ float invZ[64];
    if (threadIdx.x < 64)
        invZ[threadIdx.x] = 1.f / g_Z[b * S_DIM + s0 + threadIdx.x];
    __syncthreads();
    float a[8] = {0.f, 0.f, 0.f, 0.f, 0.f, 0.f, 0.f, 0.f};
    const __nv_bfloat16* Ep = g_E + ((size_t)b * S_DIM + s0) * S_DIM + t0;
    #pragma unroll 8
    for (int s = 0; s < 64; ++s) {
        uint4 pkt = *reinterpret_cast<const uint4*>(&Ep[(size_t)s * S_DIM]);
        const __nv_bfloat162* p2 = reinterpret_cast<const __nv_bfloat162*>(&pkt);
        float w = invZ[s];
        #pragma unroll
        for (int j = 0; j < 4; ++j) {
            float2 f = __bfloat1622float2(p2[j]);
            a[2 * j]     += f.x * w;
            a[2 * j + 1] += f.y * w;
        }
    }
    const float sc = 1.f / S_DIM;
    #pragma unroll
    for (int j = 0; j < 8; ++j)
        atomicAdd(&g_u[b * S_DIM + t0 + j], a[j] * sc);
}

// ---------------- y[b,:] = sum_t u[b,t] * x[b,t,:]  (fp32-exact V path) ----------------
__global__ void __launch_bounds__(256) pool_kernel(const float* __restrict__ x) {
    const int b = blockIdx.y, seg = blockIdx.x;
    const int e = threadIdx.x;
    __shared__ float us[128];
    if (e < 128) us[e] = g_u[b * S_DIM + seg * 128 + e];
    __syncthreads();
    float acc = 0.f;
    const float* xp = x + ((size_t)b * S_DIM + seg * 128) * E_DIM + e;
    #pragma unroll 8
    for (int tt = 0; tt < 128; ++tt) acc += us[tt] * xp[(size_t)tt * E_DIM];
    atomicAdd(&g_y[b * E_DIM + e], acc);
}

// ---------------- out[b,:] = y[b,:] @ Wv + bv ----------------
__global__ void __launch_bounds__(256) out_kernel(const float* __restrict__ Wv,
                                                  const float* __restrict__ bv,
                                                  float* __restrict__ out) {
    const int b = blockIdx.x, e = threadIdx.x;
    __shared__ float ys[256];
    ys[e] = g_y[b * E_DIM + e];
    __syncthreads();
    float acc = 0.f;
    #pragma unroll 8
    for (int j = 0; j < 256; ++j) acc += ys[j] * Wv[j * E_DIM + e];
    out[b * E_DIM + e] = acc + bv[e];
}

// ---------------- launch ----------------
extern "C" void kernel_launch(void* const* d_in, const int* in_sizes, int n_in,
                              void* d_out, int out_size) {
    (void)in_sizes; (void)n_in; (void)out_size;
    const float* x  = (const float*)d_in[0];
    const float* Wq = (const float*)d_in[1];
    const float* bq = (const float*)d_in[2];
    const float* Wk = (const float*)d_in[3];
    const float* bk = (const float*)d_in[4];
    const float* Wv = (const float*)d_in[5];
    const float* bv = (const float*)d_in[6];
    float* out = (float*)d_out;

    cudaFuncSetAttribute(scores_mma_kernel,
                         cudaFuncAttributeMaxDynamicSharedMemorySize, SCORES_SMEM);
    cudaFuncSetAttribute(proj_tc_kernel,
                         cudaFuncAttributeMaxDynamicSharedMemorySize, PROJ_SMEM);

    convert_kernel<<<256, 256>>>(Wq, Wk);
    proj_tc_kernel<<<BS_DIM / 128, 256, PROJ_SMEM>>>(x, bq, bk);
    scores_mma_kernel<<<dim3(S_DIM / 128, B_DIM), 512, SCORES_SMEM>>>();
    colreduce_kernel<<<dim3(2, 64, B_DIM), 256>>>();
    pool_kernel<<<dim3(S_DIM / 128, B_DIM), 256>>>(x);
    out_kernel<<<B_DIM, 256>>>(Wv, bv, out);
}

// round 9
// speedup vs baseline: 1.1397x; 1.0251x over previous
#include <cuda_runtime.h>
#include <cuda_bf16.h>
#include <cstdint>

#define B_DIM 4
#define S_DIM 4096
#define E_DIM 256
#define BS_DIM (B_DIM * S_DIM)

// ---------------- scratch (static __device__, no allocations) ----------------
__device__ __nv_bfloat16 g_WqT[E_DIM * E_DIM];                    // W^T bf16
__device__ __nv_bfloat16 g_WkT[E_DIM * E_DIM];
__device__ __nv_bfloat16 g_q[BS_DIM * E_DIM];                     // 8 MB
__device__ __nv_bfloat16 g_k[BS_DIM * E_DIM];                     // 8 MB
__device__ __nv_bfloat16 g_E[(size_t)B_DIM * S_DIM * S_DIM];      // 134 MB exp-scores
__device__ float g_u[B_DIM * S_DIM];                              // column means of attn
__device__ float g_y[B_DIM * E_DIM];                              // u^T x

// ================= low-level helpers =================
__device__ __forceinline__ uint32_t smem_u32(const void* p) {
    uint32_t a;
    asm("{ .reg .u64 t; cvta.to.shared.u64 t, %1; cvt.u32.u64 %0, t; }" : "=r"(a) : "l"(p));
    return a;
}

__device__ __forceinline__ void ldsm4(uint32_t (&r)[4], uint32_t addr) {
    asm volatile("ldmatrix.sync.aligned.m8n8.x4.shared.b16 {%0,%1,%2,%3}, [%4];"
                 : "=r"(r[0]), "=r"(r[1]), "=r"(r[2]), "=r"(r[3]) : "r"(addr));
}

__device__ __forceinline__ void mma16816(float (&d)[4], const uint32_t (&a)[4],
                                         uint32_t b0, uint32_t b1) {
    asm volatile("mma.sync.aligned.m16n8k16.row.col.f32.bf16.bf16.f32 "
                 "{%0,%1,%2,%3}, {%4,%5,%6,%7}, {%8,%9}, {%0,%1,%2,%3};"
                 : "+f"(d[0]), "+f"(d[1]), "+f"(d[2]), "+f"(d[3])
                 : "r"(a[0]), "r"(a[1]), "r"(a[2]), "r"(a[3]), "r"(b0), "r"(b1));
}

// swizzled address inside a 128-row x 256-col bf16 tile (blocked SW128 atoms)
__device__ __forceinline__ uint32_t swz128(uint32_t base, int r, int c16) {
    return base + (((uint32_t)(c16 >> 3)) << 14) + (((uint32_t)(r >> 3)) << 10)
                + (((uint32_t)(r & 7)) << 7) + (((uint32_t)((c16 ^ r) & 7)) << 4);
}

// Load a 128x256-bf16 tile (64KB) into the swizzled layout via cp.async (16B chunks).
template <int NT>
__device__ __forceinline__ void load_tile_async(uint32_t sm_base,
                                                const __nv_bfloat16* __restrict__ src,
                                                int tid) {
    #pragma unroll
    for (int it = 0; it < 4096 / NT; ++it) {
        int idx = it * NT + tid;           // 0..4095 16B chunks
        int r = idx >> 5;                  // row 0..127
        int g = idx & 31;                  // chunk 0..31
        uint32_t dst = swz128(sm_base, r, g);
        const void* gp = (const void*)(src + (size_t)r * E_DIM + g * 8);
        asm volatile("cp.async.cg.shared.global [%0], [%1], 16;" :: "r"(dst), "l"(gp));
    }
}
#define CPASYNC_COMMIT() asm volatile("cp.async.commit_group;" ::: "memory")
#define CPASYNC_WAIT0() asm volatile("cp.async.wait_group 0;" ::: "memory")

// warp-tile 32x32 MMA over K=256: acc[2][4][4] += A(rows mw..) * B(cols nw..)^T
__device__ __forceinline__ void mma_tile32(uint32_t Ab, uint32_t Bb, float (&acc)[2][4][4],
                                           int mw, int nw, int lane) {
    const int lane15 = lane & 15, laneh = lane >> 4;
    #pragma unroll
    for (int ks = 0; ks < 16; ++ks) {
        const int c16 = ks * 2 + laneh;
        uint32_t a[2][4], bf[2][4];
        #pragma unroll
        for (int i = 0; i < 2; ++i)
            ldsm4(a[i], swz128(Ab, mw + i * 16 + lane15, c16));
        #pragma unroll
        for (int j2 = 0; j2 < 2; ++j2)
            ldsm4(bf[j2], swz128(Bb, nw + j2 * 16 + lane15, c16));
        #pragma unroll
        for (int i = 0; i < 2; ++i)
            #pragma unroll
            for (int j = 0; j < 4; ++j)
                mma16816(acc[i][j], a[i], bf[j >> 1][j & 1], bf[j >> 1][(j & 1) + 2]);
    }
}

// ---------------- W transposes (fp32 -> bf16) + zero-init ----------------
__global__ void convert_kernel(const float* __restrict__ Wq,
                               const float* __restrict__ Wk) {
    const int tid = blockIdx.x * blockDim.x + threadIdx.x;
    if (tid < E_DIM * E_DIM) {
        int k = tid >> 8, n = tid & 255;
        g_WqT[n * E_DIM + k] = __float2bfloat16(Wq[tid]);
        g_WkT[n * E_DIM + k] = __float2bfloat16(Wk[tid]);
    }
    if (tid < B_DIM * S_DIM) g_u[tid] = 0.f;
    if (tid < B_DIM * E_DIM) g_y[tid] = 0.f;
}

// ---------------- Q/K projections (fused + inline x conversion) ----------------
#define PROJ_SMEM (196608 + 1024)
__global__ void __launch_bounds__(256) proj_tc_kernel(const float* __restrict__ x,
                                                      const float* __restrict__ bq,
                                                      const float* __restrict__ bk) {
    extern __shared__ char dynsm[];
    __shared__ float sb[4][128];
    const uint32_t base = (smem_u32(dynsm) + 1023u) & ~1023u;
    const uint32_t Ab = base;
    const uint32_t Bbuf[2] = { base + 65536u, base + 131072u };
    char* Achar = dynsm + (int)(base - smem_u32(dynsm));

    const int tid = threadIdx.x;
    const int lane = tid & 31, wid = tid >> 5;
    const int mw = (wid & 1) * 64, nw = (wid >> 1) * 32;
    const int m0 = blockIdx.x * 128;

    for (int i = tid; i < 512; i += 256)
        sb[i >> 7][i & 127] = (i >= 256 ? bk : bq)[((i >> 7) & 1) * 128 + (i & 127)];

    load_tile_async<256>(Bbuf[0], g_WqT, tid);
    CPASYNC_COMMIT();

    // inline conversion: x fp32 tile -> bf16 swizzled A
    const float* xp = x + (size_t)m0 * E_DIM;
    #pragma unroll
    for (int it = 0; it < 16; ++it) {
        int idx = it * 256 + tid;
        int r = idx >> 5, g = idx & 31;
        const float4* s = reinterpret_cast<const float4*>(xp + (size_t)r * E_DIM + g * 8);
        float4 f0 = s[0], f1 = s[1];
        __nv_bfloat162 h0 = __floats2bfloat162_rn(f0.x, f0.y);
        __nv_bfloat162 h1 = __floats2bfloat162_rn(f0.z, f0.w);
        __nv_bfloat162 h2 = __floats2bfloat162_rn(f1.x, f1.y);
        __nv_bfloat162 h3 = __floats2bfloat162_rn(f1.z, f1.w);
        uint4 pkt;
        pkt.x = *reinterpret_cast<uint32_t*>(&h0);
        pkt.y = *reinterpret_cast<uint32_t*>(&h1);
        pkt.z = *reinterpret_cast<uint32_t*>(&h2);
        pkt.w = *reinterpret_cast<uint32_t*>(&h3);
        *reinterpret_cast<uint4*>(Achar + (swz128(0, r, g))) = pkt;
    }

    #pragma unroll 1
    for (int it = 0; it < 4; ++it) {          // it: (which<<1)|nblk
        const int which = it >> 1, nblk = it & 1;
        const int n0 = nblk * 128;
        CPASYNC_WAIT0();
        __syncthreads();
        if (it + 1 < 4) {
            const int wn = (it + 1) >> 1, nb = (it + 1) & 1;
            load_tile_async<256>(Bbuf[(it + 1) & 1],
                                 (wn ? g_WkT : g_WqT) + (size_t)(nb * 128) * E_DIM, tid);
            CPASYNC_COMMIT();
        }

        float acc[2][2][4][4] = {};
        #pragma unroll
        for (int mh = 0; mh < 2; ++mh)
            mma_tile32(Ab, Bbuf[it & 1], acc[mh], mw + mh * 32, nw, lane);

        __nv_bfloat16* outp = which ? g_k : g_q;
        #pragma unroll
        for (int mh = 0; mh < 2; ++mh) {
            #pragma unroll
            for (int i = 0; i < 2; ++i) {
                #pragma unroll
                for (int h = 0; h < 2; ++h) {
                    const int r = m0 + mw + mh * 32 + i * 16 + (lane >> 2) + h * 8;
                    #pragma unroll
                    for (int j = 0; j < 4; ++j) {
                        const int cl = nw + j * 8 + (lane & 3) * 2;
                        float v0 = acc[mh][i][j][2 * h]     + sb[it][cl];
                        float v1 = acc[mh][i][j][2 * h + 1] + sb[it][cl + 1];
                        *reinterpret_cast<__nv_bfloat162*>(&outp[(size_t)r * E_DIM + n0 + cl]) =
                            __floats2bfloat162_rn(v0, v1);
                    }
                }
            }
        }
    }
}

// ---------------- scores + fused column reduce ----------------
// grid (32, 4). 512 threads, 16 warps 4x4, warp tile 32x32.
// Phase 1: E = exp(q k^T/16) for the CTA's 128 rows across all 32 n-tiles,
//          row-sum partials kept in registers.
// Phase 2 (fused colreduce): Z is complete per-CTA -> reduce in SMEM, build invZ,
//          re-read own 1MB E block (L2-warm) and atomically accumulate u partials.
#define SCORES_SMEM (196608 + 1024)
__global__ void __launch_bounds__(512, 1) scores_mma_kernel() {
    extern __shared__ char dynsm[];
    const uint32_t base = (smem_u32(dynsm) + 1023u) & ~1023u;
    const uint32_t Ab = base;
    const uint32_t Bbuf[2] = { base + 65536u, base + 131072u };
    // Z-reduction scratch lives in the B0 region (dead after iteration 30's barrier:
    // the final tile n=31 is in B1, and a __syncthreads precedes its use).
    float* zs   = reinterpret_cast<float*>(dynsm + (int)(base - smem_u32(dynsm)) + 65536);
    float* invZ = zs + 512;

    const int tid = threadIdx.x;
    const int lane = tid & 31, wid = tid >> 5;
    const int mw = (wid & 3) * 32, nw = (wid >> 2) * 32;
    const int m0 = blockIdx.x * 128;
    const int b = blockIdx.y;

    const __nv_bfloat16* Aq = g_q + (size_t)b * S_DIM * E_DIM;
    const __nv_bfloat16* Bk = g_k + (size_t)b * S_DIM * E_DIM;

    load_tile_async<512>(Ab, Aq + (size_t)m0 * E_DIM, tid);
    load_tile_async<512>(Bbuf[0], Bk, tid);
    CPASYNC_COMMIT();

    float rs[4] = {0.f, 0.f, 0.f, 0.f};
    const float SCALE = 0.09016844f;  // log2(e) / 16

    #pragma unroll 1
    for (int n = 0; n < 32; ++n) {
        CPASYNC_WAIT0();
        __syncthreads();
        if (n + 1 < 32) {
            load_tile_async<512>(Bbuf[(n + 1) & 1], Bk + (size_t)(n + 1) * 128 * E_DIM, tid);
            CPASYNC_COMMIT();
        }

        float acc[2][4][4] = {};
        mma_tile32(Ab, Bbuf[n & 1], acc, mw, nw, lane);

        // epilogue: exp(score/16) -> bf16 store + row-sum accumulation
        #pragma unroll
        for (int i = 0; i < 2; ++i) {
            #pragma unroll
            for (int h = 0; h < 2; ++h) {
                const int r = m0 + mw + i * 16 + (lane >> 2) + h * 8;
                const size_t rowb = ((size_t)b * S_DIM + r) * S_DIM
                                  + (size_t)n * 128 + nw + (lane & 3) * 2;
                float partial = 0.f;
                #pragma unroll
                for (int j = 0; j < 4; ++j) {
                    float v0, v1;
                    asm("ex2.approx.ftz.f32 %0, %1;" : "=f"(v0) : "f"(acc[i][j][2 * h] * SCALE));
                    asm("ex2.approx.ftz.f32 %0, %1;" : "=f"(v1) : "f"(acc[i][j][2 * h + 1] * SCALE));
                    partial += v0 + v1;
                    *reinterpret_cast<__nv_bfloat162*>(&g_E[rowb + j * 8]) =
                        __floats2bfloat162_rn(v0, v1);
                }
                rs[i * 2 + h] += partial;
            }
        }
    }

    // ---- Z reduction: lanes -> warps -> invZ in SMEM ----
    #pragma unroll
    for (int i = 0; i < 4; ++i) {
        rs[i] += __shfl_xor_sync(0xffffffffu, rs[i], 1);
        rs[i] += __shfl_xor_sync(0xffffffffu, rs[i], 2);
    }
    if ((lane & 3) == 0) {
        #pragma unroll
        for (int i = 0; i < 4; ++i) {
            const int row = mw + (i >> 1) * 16 + (i & 1) * 8 + (lane >> 2);
            zs[(wid >> 2) * 128 + row] = rs[i];
        }
    }
    __syncthreads();   // also makes this CTA's g_E stores visible to all its threads
    if (tid < 128)
        invZ[tid] = 1.f / (zs[tid] + zs[128 + tid] + zs[256 + tid] + zs[384 + tid]);
    __syncthreads();

    // ---- fused column reduce over this CTA's own 128 E rows (L2-warm) ----
    {
        const int t0 = tid * 8;
        float a[8] = {0.f, 0.f, 0.f, 0.f, 0.f, 0.f, 0.f, 0.f};
        const __nv_bfloat16* Ep = g_E + ((size_t)b * S_DIM + m0) * S_DIM + t0;
        #pragma unroll 8
        for (int s = 0; s < 128; ++s) {
            uint4 pkt = *reinterpret_cast<const uint4*>(&Ep[(size_t)s * S_DIM]);
            const __nv_bfloat162* p2 = reinterpret_cast<const __nv_bfloat162*>(&pkt);
            float w = invZ[s];
            #pragma unroll
            for (int j = 0; j < 4; ++j) {
                float2 f = __bfloat1622float2(p2[j]);
                a[2 * j]     += f.x * w;
                a[2 * j + 1] += f.y * w;
            }
        }
        const float sc = 1.f / S_DIM;
        #pragma unroll
        for (int j = 0; j < 8; ++j)
            atomicAdd(&g_u[b * S_DIM + t0 + j], a[j] * sc);
    }
}

// ---------------- y[b,:] = sum_t u[b,t] * x[b,t,:]  (fp32-exact V path) ----------------
__global__ void __launch_bounds__(256) pool_kernel(const float* __restrict__ x) {
    const int b = blockIdx.y, seg = blockIdx.x;
    const int e = threadIdx.x;
    __shared__ float us[128];
    if (e < 128) us[e] = g_u[b * S_DIM + seg * 128 + e];
    __syncthreads();
    float acc = 0.f;
    const float* xp = x + ((size_t)b * S_DIM + seg * 128) * E_DIM + e;
    #pragma unroll 8
    for (int tt = 0; tt < 128; ++tt) acc += us[tt] * xp[(size_t)tt * E_DIM];
    atomicAdd(&g_y[b * E_DIM + e], acc);
}

// ---------------- out[b,:] = y[b,:] @ Wv + bv ----------------
__global__ void __launch_bounds__(256) out_kernel(const float* __restrict__ Wv,
                                                  const float* __restrict__ bv,
                                                  float* __restrict__ out) {
    const int b = blockIdx.x, e = threadIdx.x;
    __shared__ float ys[256];
    ys[e] = g_y[b * E_DIM + e];
    __syncthreads();
    float acc = 0.f;
    #pragma unroll 8
    for (int j = 0; j < 256; ++j) acc += ys[j] * Wv[j * E_DIM + e];
    out[b * E_DIM + e] = acc + bv[e];
}

// ---------------- launch ----------------
extern "C" void kernel_launch(void* const* d_in, const int* in_sizes, int n_in,
                              void* d_out, int out_size) {
    (void)in_sizes; (void)n_in; (void)out_size;
    const float* x  = (const float*)d_in[0];
    const float* Wq = (const float*)d_in[1];
    const float* bq = (const float*)d_in[2];
    const float* Wk = (const float*)d_in[3];
    const float* bk = (const float*)d_in[4];
    const float* Wv = (const float*)d_in[5];
    const float* bv = (const float*)d_in[6];
    float* out = (float*)d_out;

    cudaFuncSetAttribute(scores_mma_kernel,
                         cudaFuncAttributeMaxDynamicSharedMemorySize, SCORES_SMEM);
    cudaFuncSetAttribute(proj_tc_kernel,
                         cudaFuncAttributeMaxDynamicSharedMemorySize, PROJ_SMEM);

    convert_kernel<<<256, 256>>>(Wq, Wk);
    proj_tc_kernel<<<BS_DIM / 128, 256, PROJ_SMEM>>>(x, bq, bk);
    scores_mma_kernel<<<dim3(S_DIM / 128, B_DIM), 512, SCORES_SMEM>>>();
    pool_kernel<<<dim3(S_DIM / 128, B_DIM), 256>>>(x);
    out_kernel<<<B_DIM, 256>>>(Wv, bv, out);
}

// round 10
// speedup vs baseline: 1.1812x; 1.0364x over previous
#include <cuda_runtime.h>
#include <cuda_bf16.h>
#include <cstdint>

#define B_DIM 4
#define S_DIM 4096
#define E_DIM 256
#define BS_DIM (B_DIM * S_DIM)

// ---------------- scratch (static __device__, no allocations) ----------------
__device__ __nv_bfloat16 g_WqT[E_DIM * E_DIM];                    // W^T bf16
__device__ __nv_bfloat16 g_WkT[E_DIM * E_DIM];
__device__ __nv_bfloat16 g_q[BS_DIM * E_DIM];                     // 8 MB
__device__ __nv_bfloat16 g_k[BS_DIM * E_DIM];                     // 8 MB
__device__ __nv_bfloat16 g_E[(size_t)B_DIM * S_DIM * S_DIM];      // 134 MB exp-scores
__device__ float g_u[B_DIM * S_DIM];                              // column means of attn
__device__ float g_y[B_DIM * E_DIM];                              // u^T x

// ================= low-level helpers =================
__device__ __forceinline__ uint32_t smem_u32(const void* p) {
    uint32_t a;
    asm("{ .reg .u64 t; cvta.to.shared.u64 t, %1; cvt.u32.u64 %0, t; }" : "=r"(a) : "l"(p));
    return a;
}

__device__ __forceinline__ void ldsm4(uint32_t (&r)[4], uint32_t addr) {
    asm volatile("ldmatrix.sync.aligned.m8n8.x4.shared.b16 {%0,%1,%2,%3}, [%4];"
                 : "=r"(r[0]), "=r"(r[1]), "=r"(r[2]), "=r"(r[3]) : "r"(addr));
}

__device__ __forceinline__ void mma16816(float (&d)[4], const uint32_t (&a)[4],
                                         uint32_t b0, uint32_t b1) {
    asm volatile("mma.sync.aligned.m16n8k16.row.col.f32.bf16.bf16.f32 "
                 "{%0,%1,%2,%3}, {%4,%5,%6,%7}, {%8,%9}, {%0,%1,%2,%3};"
                 : "+f"(d[0]), "+f"(d[1]), "+f"(d[2]), "+f"(d[3])
                 : "r"(a[0]), "r"(a[1]), "r"(a[2]), "r"(a[3]), "r"(b0), "r"(b1));
}

// swizzled address inside a 128-row x 256-col bf16 tile (blocked SW128 atoms)
__device__ __forceinline__ uint32_t swz128(uint32_t base, int r, int c16) {
    return base + (((uint32_t)(c16 >> 3)) << 14) + (((uint32_t)(r >> 3)) << 10)
                + (((uint32_t)(r & 7)) << 7) + (((uint32_t)((c16 ^ r) & 7)) << 4);
}

// Load a 128x256-bf16 tile (64KB) into the swizzled layout via cp.async (16B chunks).
template <int NT>
__device__ __forceinline__ void load_tile_async(uint32_t sm_base,
                                                const __nv_bfloat16* __restrict__ src,
                                                int tid) {
    #pragma unroll
    for (int it = 0; it < 4096 / NT; ++it) {
        int idx = it * NT + tid;           // 0..4095 16B chunks
        int r = idx >> 5;                  // row 0..127
        int g = idx & 31;                  // chunk 0..31
        uint32_t dst = swz128(sm_base, r, g);
        const void* gp = (const void*)(src + (size_t)r * E_DIM + g * 8);
        asm volatile("cp.async.cg.shared.global [%0], [%1], 16;" :: "r"(dst), "l"(gp));
    }
}
#define CPASYNC_COMMIT() asm volatile("cp.async.commit_group;" ::: "memory")
#define CPASYNC_WAIT0() asm volatile("cp.async.wait_group 0;" ::: "memory")

// warp-tile 32x32 MMA over K=256: acc[2][4][4] += A(rows mw..) * B(cols nw..)^T
__device__ __forceinline__ void mma_tile32(uint32_t Ab, uint32_t Bb, float (&acc)[2][4][4],
                                           int mw, int nw, int lane) {
    const int lane15 = lane & 15, laneh = lane >> 4;
    #pragma unroll
    for (int ks = 0; ks < 16; ++ks) {
        const int c16 = ks * 2 + laneh;
        uint32_t a[2][4], bf[2][4];
        #pragma unroll
        for (int i = 0; i < 2; ++i)
            ldsm4(a[i], swz128(Ab, mw + i * 16 + lane15, c16));
        #pragma unroll
        for (int j2 = 0; j2 < 2; ++j2)
            ldsm4(bf[j2], swz128(Bb, nw + j2 * 16 + lane15, c16));
        #pragma unroll
        for (int i = 0; i < 2; ++i)
            #pragma unroll
            for (int j = 0; j < 4; ++j)
                mma16816(acc[i][j], a[i], bf[j >> 1][j & 1], bf[j >> 1][(j & 1) + 2]);
    }
}

// ---------------- W transposes (fp32 -> bf16) + zero-init ----------------
__global__ void convert_kernel(const float* __restrict__ Wq,
                               const float* __restrict__ Wk) {
    const int tid = blockIdx.x * blockDim.x + threadIdx.x;
    if (tid < E_DIM * E_DIM) {
        int k = tid >> 8, n = tid & 255;
        g_WqT[n * E_DIM + k] = __float2bfloat16(Wq[tid]);
        g_WkT[n * E_DIM + k] = __float2bfloat16(Wk[tid]);
    }
    if (tid < B_DIM * S_DIM) g_u[tid] = 0.f;
    if (tid < B_DIM * E_DIM) g_y[tid] = 0.f;
}

// ---------------- Q/K projections (fused + inline x conversion) ----------------
#define PROJ_SMEM (196608 + 1024)
__global__ void __launch_bounds__(256) proj_tc_kernel(const float* __restrict__ x,
                                                      const float* __restrict__ bq,
                                                      const float* __restrict__ bk) {
    extern __shared__ char dynsm[];
    __shared__ float sb[4][128];
    const uint32_t base = (smem_u32(dynsm) + 1023u) & ~1023u;
    const uint32_t Ab = base;
    const uint32_t Bbuf[2] = { base + 65536u, base + 131072u };
    char* Achar = dynsm + (int)(base - smem_u32(dynsm));

    const int tid = threadIdx.x;
    const int lane = tid & 31, wid = tid >> 5;
    const int mw = (wid & 1) * 64, nw = (wid >> 1) * 32;
    const int m0 = blockIdx.x * 128;

    for (int i = tid; i < 512; i += 256)
        sb[i >> 7][i & 127] = (i >= 256 ? bk : bq)[((i >> 7) & 1) * 128 + (i & 127)];

    load_tile_async<256>(Bbuf[0], g_WqT, tid);
    CPASYNC_COMMIT();

    // inline conversion: x fp32 tile -> bf16 swizzled A
    const float* xp = x + (size_t)m0 * E_DIM;
    #pragma unroll
    for (int it = 0; it < 16; ++it) {
        int idx = it * 256 + tid;
        int r = idx >> 5, g = idx & 31;
        const float4* s = reinterpret_cast<const float4*>(xp + (size_t)r * E_DIM + g * 8);
        float4 f0 = s[0], f1 = s[1];
        __nv_bfloat162 h0 = __floats2bfloat162_rn(f0.x, f0.y);
        __nv_bfloat162 h1 = __floats2bfloat162_rn(f0.z, f0.w);
        __nv_bfloat162 h2 = __floats2bfloat162_rn(f1.x, f1.y);
        __nv_bfloat162 h3 = __floats2bfloat162_rn(f1.z, f1.w);
        uint4 pkt;
        pkt.x = *reinterpret_cast<uint32_t*>(&h0);
        pkt.y = *reinterpret_cast<uint32_t*>(&h1);
        pkt.z = *reinterpret_cast<uint32_t*>(&h2);
        pkt.w = *reinterpret_cast<uint32_t*>(&h3);
        *reinterpret_cast<uint4*>(Achar + (swz128(0, r, g))) = pkt;
    }

    #pragma unroll 1
    for (int it = 0; it < 4; ++it) {          // it: (which<<1)|nblk
        const int which = it >> 1, nblk = it & 1;
        const int n0 = nblk * 128;
        CPASYNC_WAIT0();
        __syncthreads();
        if (it + 1 < 4) {
            const int wn = (it + 1) >> 1, nb = (it + 1) & 1;
            load_tile_async<256>(Bbuf[(it + 1) & 1],
                                 (wn ? g_WkT : g_WqT) + (size_t)(nb * 128) * E_DIM, tid);
            CPASYNC_COMMIT();
        }

        float acc[2][2][4][4] = {};
        #pragma unroll
        for (int mh = 0; mh < 2; ++mh)
            mma_tile32(Ab, Bbuf[it & 1], acc[mh], mw + mh * 32, nw, lane);

        __nv_bfloat16* outp = which ? g_k : g_q;
        #pragma unroll
        for (int mh = 0; mh < 2; ++mh) {
            #pragma unroll
            for (int i = 0; i < 2; ++i) {
                #pragma unroll
                for (int h = 0; h < 2; ++h) {
                    const int r = m0 + mw + mh * 32 + i * 16 + (lane >> 2) + h * 8;
                    #pragma unroll
                    for (int j = 0; j < 4; ++j) {
                        const int cl = nw + j * 8 + (lane & 3) * 2;
                        float v0 = acc[mh][i][j][2 * h]     + sb[it][cl];
                        float v1 = acc[mh][i][j][2 * h + 1] + sb[it][cl + 1];
                        *reinterpret_cast<__nv_bfloat162*>(&outp[(size_t)r * E_DIM + n0 + cl]) =
                            __floats2bfloat162_rn(v0, v1);
                    }
                }
            }
        }
    }
}

// ---------------- scores + fused column reduce ----------------
#define SCORES_SMEM (196608 + 1024)
__global__ void __launch_bounds__(512, 1) scores_mma_kernel() {
    extern __shared__ char dynsm[];
    const uint32_t base = (smem_u32(dynsm) + 1023u) & ~1023u;
    const uint32_t Ab = base;
    const uint32_t Bbuf[2] = { base + 65536u, base + 131072u };
    // Z-reduction scratch lives in the B0 region (dead after iteration 30's barrier:
    // the final tile n=31 is in B1, and a __syncthreads precedes its use).
    float* zs   = reinterpret_cast<float*>(dynsm + (int)(base - smem_u32(dynsm)) + 65536);
    float* invZ = zs + 512;

    const int tid = threadIdx.x;
    const int lane = tid & 31, wid = tid >> 5;
    const int mw = (wid & 3) * 32, nw = (wid >> 2) * 32;
    const int m0 = blockIdx.x * 128;
    const int b = blockIdx.y;

    const __nv_bfloat16* Aq = g_q + (size_t)b * S_DIM * E_DIM;
    const __nv_bfloat16* Bk = g_k + (size_t)b * S_DIM * E_DIM;

    load_tile_async<512>(Ab, Aq + (size_t)m0 * E_DIM, tid);
    load_tile_async<512>(Bbuf[0], Bk, tid);
    CPASYNC_COMMIT();

    float rs[4] = {0.f, 0.f, 0.f, 0.f};
    const float SCALE = 0.09016844f;  // log2(e) / 16

    #pragma unroll 1
    for (int n = 0; n < 32; ++n) {
        CPASYNC_WAIT0();
        __syncthreads();
        if (n + 1 < 32) {
            load_tile_async<512>(Bbuf[(n + 1) & 1], Bk + (size_t)(n + 1) * 128 * E_DIM, tid);
            CPASYNC_COMMIT();
        }

        float acc[2][4][4] = {};
        mma_tile32(Ab, Bbuf[n & 1], acc, mw, nw, lane);

        // epilogue: exp(score/16) -> bf16 store + row-sum accumulation
        #pragma unroll
        for (int i = 0; i < 2; ++i) {
            #pragma unroll
            for (int h = 0; h < 2; ++h) {
                const int r = m0 + mw + i * 16 + (lane >> 2) + h * 8;
                const size_t rowb = ((size_t)b * S_DIM + r) * S_DIM
                                  + (size_t)n * 128 + nw + (lane & 3) * 2;
                float partial = 0.f;
                #pragma unroll
                for (int j = 0; j < 4; ++j) {
                    float v0, v1;
                    asm("ex2.approx.ftz.f32 %0, %1;" : "=f"(v0) : "f"(acc[i][j][2 * h] * SCALE));
                    asm("ex2.approx.ftz.f32 %0, %1;" : "=f"(v1) : "f"(acc[i][j][2 * h + 1] * SCALE));
                    partial += v0 + v1;
                    *reinterpret_cast<__nv_bfloat162*>(&g_E[rowb + j * 8]) =
                        __floats2bfloat162_rn(v0, v1);
                }
                rs[i * 2 + h] += partial;
            }
        }
    }

    // ---- Z reduction: lanes -> warps -> invZ in SMEM ----
    #pragma unroll
    for (int i = 0; i < 4; ++i) {
        rs[i] += __shfl_xor_sync(0xffffffffu, rs[i], 1);
        rs[i] += __shfl_xor_sync(0xffffffffu, rs[i], 2);
    }
    if ((lane & 3) == 0) {
        #pragma unroll
        for (int i = 0; i < 4; ++i) {
            const int row = mw + (i >> 1) * 16 + (i & 1) * 8 + (lane >> 2);
            zs[(wid >> 2) * 128 + row] = rs[i];
        }
    }
    __syncthreads();   // also makes this CTA's g_E stores visible to all its threads
    if (tid < 128)
        invZ[tid] = 1.f / (zs[tid] + zs[128 + tid] + zs[256 + tid] + zs[384 + tid]);
    __syncthreads();

    // ---- fused column reduce over this CTA's own 128 E rows ----
    // Two independent 64-row chains per thread for doubled load-level parallelism.
    {
        const int t0 = tid * 8;
        float a0[8] = {0.f, 0.f, 0.f, 0.f, 0.f, 0.f, 0.f, 0.f};
        float a1[8] = {0.f, 0.f, 0.f, 0.f, 0.f, 0.f, 0.f, 0.f};
        const __nv_bfloat16* Ep0 = g_E + ((size_t)b * S_DIM + m0) * S_DIM + t0;
        const __nv_bfloat16* Ep1 = Ep0 + (size_t)64 * S_DIM;
        #pragma unroll 4
        for (int s = 0; s < 64; ++s) {
            uint4 p0 = *reinterpret_cast<const uint4*>(&Ep0[(size_t)s * S_DIM]);
            uint4 p1 = *reinterpret_cast<const uint4*>(&Ep1[(size_t)s * S_DIM]);
            const __nv_bfloat162* q0 = reinterpret_cast<const __nv_bfloat162*>(&p0);
            const __nv_bfloat162* q1 = reinterpret_cast<const __nv_bfloat162*>(&p1);
            float w0 = invZ[s], w1 = invZ[64 + s];
            #pragma unroll
            for (int j = 0; j < 4; ++j) {
                float2 f0 = __bfloat1622float2(q0[j]);
                float2 f1 = __bfloat1622float2(q1[j]);
                a0[2 * j]     += f0.x * w0;
                a0[2 * j + 1] += f0.y * w0;
                a1[2 * j]     += f1.x * w1;
                a1[2 * j + 1] += f1.y * w1;
            }
        }
        const float sc = 1.f / S_DIM;
        #pragma unroll
        for (int j = 0; j < 8; ++j)
            atomicAdd(&g_u[b * S_DIM + t0 + j], (a0[j] + a1[j]) * sc);
    }
}

// ---------------- y[b,:] = sum_t u[b,t] * x[b,t,:]  (fp32-exact V path) ----------------
// grid (128, 4) = 512 CTAs; 32-row segments for occupancy/MLP.
__global__ void __launch_bounds__(256) pool_kernel(const float* __restrict__ x) {
    const int b = blockIdx.y, seg = blockIdx.x;
    const int e = threadIdx.x;
    __shared__ float us[32];
    if (e < 32) us[e] = g_u[b * S_DIM + seg * 32 + e];
    __syncthreads();
    float acc = 0.f;
    const float* xp = x + ((size_t)b * S_DIM + seg * 32) * E_DIM + e;
    #pragma unroll 8
    for (int tt = 0; tt < 32; ++tt) acc += us[tt] * xp[(size_t)tt * E_DIM];
    atomicAdd(&g_y[b * E_DIM + e], acc);
}

// ---------------- out[b,:] = y[b,:] @ Wv + bv ----------------
__global__ void __launch_bounds__(256) out_kernel(const float* __restrict__ Wv,
                                                  const float* __restrict__ bv,
                                                  float* __restrict__ out) {
    const int b = blockIdx.x, e = threadIdx.x;
    __shared__ float ys[256];
    ys[e] = g_y[b * E_DIM + e];
    __syncthreads();
    float acc = 0.f;
    #pragma unroll 8
    for (int j = 0; j < 256; ++j) acc += ys[j] * Wv[j * E_DIM + e];
    out[b * E_DIM + e] = acc + bv[e];
}

// ---------------- launch ----------------
extern "C" void kernel_launch(void* const* d_in, const int* in_sizes, int n_in,
                              void* d_out, int out_size) {
    (void)in_sizes; (void)n_in; (void)out_size;
    const float* x  = (const float*)d_in[0];
    const float* Wq = (const float*)d_in[1];
    const float* bq = (const float*)d_in[2];
    const float* Wk = (const float*)d_in[3];
    const float* bk = (const float*)d_in[4];
    const float* Wv = (const float*)d_in[5];
    const float* bv = (const float*)d_in[6];
    float* out = (float*)d_out;

    cudaFuncSetAttribute(scores_mma_kernel,
                         cudaFuncAttributeMaxDynamicSharedMemorySize, SCORES_SMEM);
    cudaFuncSetAttribute(proj_tc_kernel,
                         cudaFuncAttributeMaxDynamicSharedMemorySize, PROJ_SMEM);

    convert_kernel<<<256, 256>>>(Wq, Wk);
    proj_tc_kernel<<<BS_DIM / 128, 256, PROJ_SMEM>>>(x, bq, bk);
    scores_mma_kernel<<<dim3(S_DIM / 128, B_DIM), 512, SCORES_SMEM>>>();
    pool_kernel<<<dim3(S_DIM / 32, B_DIM), 256>>>(x);
    out_kernel<<<B_DIM, 256>>>(Wv, bv, out);
}